// round 12
// baseline (speedup 1.0000x reference)
#include <cuda_runtime.h>
#include <cstdint>

// CutOut: fused single kernel, persistent-CTA variant.
// images: (B=64, H=512, W=512, C=3) fp32.  Row = 1536 floats = 384 float4s.
// 444 persistent blocks (148 SMs x 3 CTAs) x 384 threads grid-stride over
// 4096 row-groups of 8 rows each.  Inner structure = measured best:
// MLP=8 front-batched __ldg float4 loads, __stcs streaming stores.
// Labels (int32 -> float32) fused into block 0.

#define Bsz  64
#define Hsz  512
#define Wsz  512
#define Csz  3
#define HALF 25
#define ROW_FLOATS   (Wsz * Csz)       // 1536
#define ROW_VEC4     (ROW_FLOATS / 4)  // 384
#define TOTAL_FLOATS (Bsz * Hsz * ROW_FLOATS)
#define ROWS_PER_BLK 8
#define N_GROUPS     ((Bsz * Hsz) / ROWS_PER_BLK)  // 4096
#define GRID_BLKS    444                            // 148 SMs x 3 CTAs

__global__ __launch_bounds__(ROW_VEC4)
void cutout_kernel(const float4* __restrict__ in,
                   float4* __restrict__ out,
                   const int* __restrict__ labels,
                   const int* __restrict__ center_h,
                   const int* __restrict__ center_w)
{
    const int t = threadIdx.x;

    // Fused labels pass-through (int32 -> float32), once, by block 0.
    if (blockIdx.x == 0 && t < Bsz) {
        float* tail = (float*)out + TOTAL_FLOATS;
        tail[t] = (float)__ldg(&labels[t]);
    }

    for (int g = blockIdx.x; g < N_GROUPS; g += GRID_BLKS) {
        const int row0 = g * ROWS_PER_BLK;        // first global row
        const int b  = row0 >> 9;                 // / 512 (8 rows same image)
        const int h0 = row0 & (Hsz - 1);          // % 512

        const long base = (long)row0 * ROW_VEC4 + t;

        // Front-batched loads: 8 outstanding float4 loads per thread.
        float4 v[ROWS_PER_BLK];
#pragma unroll
        for (int r = 0; r < ROWS_PER_BLK; r++)
            v[r] = __ldg(&in[base + (long)r * ROW_VEC4]);

        const int ch = __ldg(&center_h[b]);
        const int h_lo = ch - HALF, h_hi = ch + HALF;

        // Does any of our 8 rows intersect the vertical band?
        if (h0 + ROWS_PER_BLK > h_lo && h0 < h_hi) {
            const int cw = __ldg(&center_w[b]);
            const int w_lo = cw - HALF, w_hi = cw + HALF;
            const int e0 = t * 4;
            int w;
            w = e0 / 3;        const bool mx = (w >= w_lo) && (w < w_hi);
            w = (e0 + 1) / 3;  const bool my = (w >= w_lo) && (w < w_hi);
            w = (e0 + 2) / 3;  const bool mz = (w >= w_lo) && (w < w_hi);
            w = (e0 + 3) / 3;  const bool mw = (w >= w_lo) && (w < w_hi);

#pragma unroll
            for (int r = 0; r < ROWS_PER_BLK; r++) {
                if (h0 + r >= h_lo && h0 + r < h_hi) {
                    if (mx) v[r].x = 0.f;
                    if (my) v[r].y = 0.f;
                    if (mz) v[r].z = 0.f;
                    if (mw) v[r].w = 0.f;
                }
            }
        }

#pragma unroll
        for (int r = 0; r < ROWS_PER_BLK; r++)
            __stcs(&out[base + (long)r * ROW_VEC4], v[r]);
    }
}

extern "C" void kernel_launch(void* const* d_in, const int* in_sizes, int n_in,
                              void* d_out, int out_size)
{
    const float* images   = (const float*)d_in[0];
    const int*   labels   = (const int*)d_in[1];
    const int*   center_h = (const int*)d_in[2];
    const int*   center_w = (const int*)d_in[3];

    float* out = (float*)d_out;

    cutout_kernel<<<GRID_BLKS, ROW_VEC4>>>(
        (const float4*)images, (float4*)out, labels, center_h, center_w);
}

// round 13
// speedup vs baseline: 1.1327x; 1.1327x over previous
#include <cuda_runtime.h>
#include <cstdint>

// CutOut — FINAL configuration (best measured: 62.5us total, 55.8us kernel,
// 78% DRAM). images: (B=64, H=512, W=512, C=3) fp32.  Row = 1536 floats =
// 384 float4s.  One 384-thread block handles 8 consecutive rows of one image
// (MLP=8 front-batched __ldg loads, __stcs streaming stores); grid = 4096.
// Measured design space: MLP{1,4,8,16}: 8 optimal; v8-256bit ~= float4;
// CE-memcpy route neutral-worse; persistent CTAs regressed; evict-normal
// loads +1us over __ldcs.  Labels (int32 -> float32) fused into block 0.

#define Bsz  64
#define Hsz  512
#define Wsz  512
#define Csz  3
#define HALF 25
#define ROW_FLOATS   (Wsz * Csz)       // 1536
#define ROW_VEC4     (ROW_FLOATS / 4)  // 384
#define TOTAL_FLOATS (Bsz * Hsz * ROW_FLOATS)
#define ROWS_PER_BLK 8

__global__ __launch_bounds__(ROW_VEC4)
void cutout_kernel(const float4* __restrict__ in,
                   float4* __restrict__ out,
                   const int* __restrict__ labels,
                   const int* __restrict__ center_h,
                   const int* __restrict__ center_w)
{
    const int t = threadIdx.x;

    // Fused labels pass-through (int32 -> float32), once, by block 0.
    // Issued before the load burst so its latency hides under the stream.
    if (blockIdx.x == 0 && t < Bsz) {
        float* tail = (float*)out + TOTAL_FLOATS;
        tail[t] = (float)__ldg(&labels[t]);
    }

    const int row0 = blockIdx.x * ROWS_PER_BLK;   // first global row
    const int b  = row0 >> 9;                     // / 512 (8 rows same image)
    const int h0 = row0 & (Hsz - 1);              // % 512

    const long base = (long)row0 * ROW_VEC4 + t;

    // Front-batched loads: 8 outstanding float4 loads per thread, evict-normal.
    float4 v[ROWS_PER_BLK];
#pragma unroll
    for (int r = 0; r < ROWS_PER_BLK; r++)
        v[r] = __ldg(&in[base + (long)r * ROW_VEC4]);

    const int ch = __ldg(&center_h[b]);
    const int h_lo = ch - HALF, h_hi = ch + HALF;

    // Does any of our 8 rows intersect the vertical band?
    if (h0 + ROWS_PER_BLK > h_lo && h0 < h_hi) {
        const int cw = __ldg(&center_w[b]);
        const int w_lo = cw - HALF, w_hi = cw + HALF;
        const int e0 = t * 4;
        int w;
        w = e0 / 3;        const bool mx = (w >= w_lo) && (w < w_hi);
        w = (e0 + 1) / 3;  const bool my = (w >= w_lo) && (w < w_hi);
        w = (e0 + 2) / 3;  const bool mz = (w >= w_lo) && (w < w_hi);
        w = (e0 + 3) / 3;  const bool mw = (w >= w_lo) && (w < w_hi);

#pragma unroll
        for (int r = 0; r < ROWS_PER_BLK; r++) {
            if (h0 + r >= h_lo && h0 + r < h_hi) {
                if (mx) v[r].x = 0.f;
                if (my) v[r].y = 0.f;
                if (mz) v[r].z = 0.f;
                if (mw) v[r].w = 0.f;
            }
        }
    }

#pragma unroll
    for (int r = 0; r < ROWS_PER_BLK; r++)
        __stcs(&out[base + (long)r * ROW_VEC4], v[r]);
}

extern "C" void kernel_launch(void* const* d_in, const int* in_sizes, int n_in,
                              void* d_out, int out_size)
{
    const float* images   = (const float*)d_in[0];
    const int*   labels   = (const int*)d_in[1];
    const int*   center_h = (const int*)d_in[2];
    const int*   center_w = (const int*)d_in[3];

    float* out = (float*)d_out;

    cutout_kernel<<<(Bsz * Hsz) / ROWS_PER_BLK, ROW_VEC4>>>(
        (const float4*)images, (float4*)out, labels, center_h, center_w);
}

// round 14
// speedup vs baseline: 1.1344x; 1.0015x over previous
#include <cuda_runtime.h>
#include <cstdint>

// CutOut — FINAL (converged).  Best measured: 55.5us kernel / 62.5us total,
// 78.7% DRAM (6.24 TB/s), the chip's mixed read+write stream ceiling
// (verified path-independent across SM-float4, SM-v8, CE-memcpy).
// images: (B=64, H=512, W=512, C=3) fp32.  Row = 1536 floats = 384 float4s.
// One 384-thread block handles 8 consecutive rows of one image (MLP=8
// front-batched __ldg loads — evict-normal for cross-replay L2 reuse —
// and __stcs streaming stores); grid = B*H/8 = 4096.
// Design space measured: MLP{1,4,8,16}: 8 optimal; persistent CTAs regress;
// split labels kernel costs 1.8us; __ldcs loads cost 1us.
// Labels (int32 -> float32) fused into block 0.

#define Bsz  64
#define Hsz  512
#define Wsz  512
#define Csz  3
#define HALF 25
#define ROW_FLOATS   (Wsz * Csz)       // 1536
#define ROW_VEC4     (ROW_FLOATS / 4)  // 384
#define TOTAL_FLOATS (Bsz * Hsz * ROW_FLOATS)
#define ROWS_PER_BLK 8

__global__ __launch_bounds__(ROW_VEC4)
void cutout_kernel(const float4* __restrict__ in,
                   float4* __restrict__ out,
                   const int* __restrict__ labels,
                   const int* __restrict__ center_h,
                   const int* __restrict__ center_w)
{
    const int t = threadIdx.x;

    // Fused labels pass-through (int32 -> float32), once, by block 0.
    if (blockIdx.x == 0 && t < Bsz) {
        float* tail = (float*)out + TOTAL_FLOATS;
        tail[t] = (float)__ldg(&labels[t]);
    }

    const int row0 = blockIdx.x * ROWS_PER_BLK;   // first global row
    const int b  = row0 >> 9;                     // / 512 (8 rows same image)
    const int h0 = row0 & (Hsz - 1);              // % 512

    const long base = (long)row0 * ROW_VEC4 + t;

    // Front-batched loads: 8 outstanding float4 loads per thread, evict-normal.
    float4 v[ROWS_PER_BLK];
#pragma unroll
    for (int r = 0; r < ROWS_PER_BLK; r++)
        v[r] = __ldg(&in[base + (long)r * ROW_VEC4]);

    const int ch = __ldg(&center_h[b]);
    const int h_lo = ch - HALF, h_hi = ch + HALF;

    // Does any of our 8 rows intersect the vertical band?
    if (h0 + ROWS_PER_BLK > h_lo && h0 < h_hi) {
        const int cw = __ldg(&center_w[b]);
        const int w_lo = cw - HALF, w_hi = cw + HALF;
        const int e0 = t * 4;
        int w;
        w = e0 / 3;        const bool mx = (w >= w_lo) && (w < w_hi);
        w = (e0 + 1) / 3;  const bool my = (w >= w_lo) && (w < w_hi);
        w = (e0 + 2) / 3;  const bool mz = (w >= w_lo) && (w < w_hi);
        w = (e0 + 3) / 3;  const bool mw = (w >= w_lo) && (w < w_hi);

#pragma unroll
        for (int r = 0; r < ROWS_PER_BLK; r++) {
            if (h0 + r >= h_lo && h0 + r < h_hi) {
                if (mx) v[r].x = 0.f;
                if (my) v[r].y = 0.f;
                if (mz) v[r].z = 0.f;
                if (mw) v[r].w = 0.f;
            }
        }
    }

#pragma unroll
    for (int r = 0; r < ROWS_PER_BLK; r++)
        __stcs(&out[base + (long)r * ROW_VEC4], v[r]);
}

extern "C" void kernel_launch(void* const* d_in, const int* in_sizes, int n_in,
                              void* d_out, int out_size)
{
    const float* images   = (const float*)d_in[0];
    const int*   labels   = (const int*)d_in[1];
    const int*   center_h = (const int*)d_in[2];
    const int*   center_w = (const int*)d_in[3];

    float* out = (float*)d_out;

    cutout_kernel<<<(Bsz * Hsz) / ROWS_PER_BLK, ROW_VEC4>>>(
        (const float4*)images, (float4*)out, labels, center_h, center_w);
}